// round 10
// baseline (speedup 1.0000x reference)
#include <cuda_runtime.h>

// lut_kernel_49538152792187 — 6-bit soft-LUT layer.
// x: [16, 2, 1024, 384] f32   out: [16, 2, 1024, 64] f32
// w: [1024, 64, 64]     f32
//
// TWO threads per (out, lut): each owns one 32-entry half-subtree
// (tree levels 0-4); halves combined at level 5 via shfl. Levels 0+1
// folded into a bilinear table (c0..c3 per 4-entry group, 32 regs):
//   y = c0 + b0*c1 + b1*c2 + (b0*b1)*c3        (3 FFMA / group)
// 4096 warps (~26/SM); w read exactly once; x deduped in-warp via
// broadcast. DEPTH-2 x-load pipeline: iteration i consumes slot i&1
// while loads for i+2 are in flight (~1140 cyc cover vs 577 DRAM lat).

#define BR 32

__device__ __forceinline__ float sig2(float v) {
    // (tanh(v)+1)/2 == 1/(1+exp(-2v)); randn v -> bounded, no overflow.
    float e = __expf(-2.0f * v);
    return __fdividef(1.0f, 1.0f + e);
}

__global__ void __launch_bounds__(64, 13)
lut_kernel(const float* __restrict__ x, const float* __restrict__ w,
           float* __restrict__ out) {
    const int g    = blockIdx.x * 64 + threadIdx.x;   // 0..131071
    const int half = g & 1;                           // subtree half
    const int ol   = g >> 1;                          // o*64 + lut, 0..65535
    const int lut  = ol & 63;
    const int o    = ol >> 6;

    // ---- load 32-entry half table, wq = sigmoid(2w), fold levels 0+1 ----
    const float4* wp = reinterpret_cast<const float4*>(
        w + (size_t)ol * 64 + half * 32);
    float c0[8], c1[8], c2[8], c3[8];
#pragma unroll
    for (int m = 0; m < 8; m++) {
        float4 v = wp[m];
        float q0 = sig2(v.x), q1 = sig2(v.y), q2 = sig2(v.z), q3 = sig2(v.w);
        c0[m] = q0;
        c1[m] = q1 - q0;
        c2[m] = q2 - q0;
        c3[m] = ((q3 - q2) - q1) + q0;
    }

    const float* xp = x + (size_t)o * 384 + lut * 6;  // 8B-aligned
    float*       op = out + (size_t)ol;
    const size_t xs = (size_t)1024 * 384;
    const size_t os = (size_t)1024 * 64;

    // ---- depth-2 prefetch: slots for iters i and i+1 in flight ----
    float2 A0[2], A1[2], A2[2];
    A0[0] = *reinterpret_cast<const float2*>(xp);
    A1[0] = *reinterpret_cast<const float2*>(xp + 2);
    A2[0] = *reinterpret_cast<const float2*>(xp + 4);
    xp += xs;
    A0[1] = *reinterpret_cast<const float2*>(xp);
    A1[1] = *reinterpret_cast<const float2*>(xp + 2);
    A2[1] = *reinterpret_cast<const float2*>(xp + 4);
    xp += xs;

#pragma unroll 4
    for (int br = 0; br < BR; br++) {
        const int s = br & 1;                         // static under unroll
        const float B0 = A0[s].x, B1 = A0[s].y, B2 = A1[s].x,
                    B3 = A1[s].y, B4 = A2[s].x, B5 = A2[s].y;
        if (br + 2 < BR) {                 // issue loads for iter br+2
            A0[s] = *reinterpret_cast<const float2*>(xp);
            A1[s] = *reinterpret_cast<const float2*>(xp + 2);
            A2[s] = *reinterpret_cast<const float2*>(xp + 4);
            xp += xs;
        }

        // levels 0+1 via bilinear table: 8 groups
        const float t01 = B0 * B1;
        float ym[8];
#pragma unroll
        for (int m = 0; m < 8; m++)
            ym[m] = fmaf(t01, c3[m], fmaf(B1, c2[m], fmaf(B0, c1[m], c0[m])));

        // level 2
        float z0 = fmaf(B2, ym[1] - ym[0], ym[0]);
        float z1 = fmaf(B2, ym[3] - ym[2], ym[2]);
        float z2 = fmaf(B2, ym[5] - ym[4], ym[4]);
        float z3 = fmaf(B2, ym[7] - ym[6], ym[6]);
        // level 3
        float u0 = fmaf(B3, z1 - z0, z0);
        float u1 = fmaf(B3, z3 - z2, z2);
        // level 4: this half-subtree's value
        float v = fmaf(B4, u1 - u0, u0);

        // level 5: combine halves (even lane = low half, odd = high half)
        float vhi = __shfl_down_sync(0xffffffffu, v, 1);
        if (half == 0) *op = fmaf(B5, vhi - v, v);
        op += os;
    }
}

extern "C" void kernel_launch(void* const* d_in, const int* in_sizes, int n_in,
                              void* d_out, int out_size) {
    const float* x = (const float*)d_in[0];
    const float* w = (const float*)d_in[1];
    float* out = (float*)d_out;
    lut_kernel<<<2048, 64>>>(x, w, out);
}